// round 4
// baseline (speedup 1.0000x reference)
#include <cuda_runtime.h>
#include <cuda_fp16.h>
#include <cstdint>
#include <math.h>

// ---------------- problem dims ----------------
#define BB    1024
#define DIN   2048
#define DINT  8192
#define NGIN  16          // DIN/128
#define NGINT 64          // DINT/128

// ---------------- scratch (device globals; no allocation allowed) ----------------
__device__ __half g_x_h  [BB * DIN];              // x in fp16
__device__ __half g_rotg_h[NGIN  * 128 * 128];
__device__ __half g_rotu_h[NGIN  * 128 * 128];
__device__ __half g_rotd_h[NGINT * 128 * 128];
__device__ __half g_Wg   [DINT * DIN];            // dequantized, scaled weights
__device__ __half g_Wu   [DINT * DIN];
__device__ __half g_Wd   [DIN * DINT];
__device__ __half g_xrg  [BB * DIN];              // rotated x (gate path)
__device__ __half g_xru  [BB * DIN];              // rotated x (up path)
__device__ __half g_gate [BB * DINT];             // gate + bias (pre-silu), fp16
__device__ __half g_h    [BB * DINT];             // silu(gate)*up
__device__ __half g_hr   [BB * DINT];             // rotated h

// ---------------- small kernels ----------------
__global__ void k_convert(const float4* __restrict__ in, __half2* __restrict__ out, int n4) {
    int i = blockIdx.x * blockDim.x + threadIdx.x;
    if (i >= n4) return;
    float4 v = in[i];
    out[2 * i]     = __floats2half2_rn(v.x, v.y);
    out[2 * i + 1] = __floats2half2_rn(v.z, v.w);
}

__device__ __forceinline__ uint32_t pack2(int v, const float* lut, float s) {
    __half2 h = __floats2half2_rn(lut[v & 15] * s, lut[(v >> 4) & 15] * s);
    return *reinterpret_cast<uint32_t*>(&h);
}

// Each thread: 4 packed int32 (one byte each = 2 nibbles) -> 8 fp16 weights.
__global__ void k_dequant(const int* __restrict__ packed, const float* __restrict__ cb,
                          const float* __restrict__ norms, __half* __restrict__ out,
                          int N, int K) {
    __shared__ float lut[16];
    if (threadIdx.x < 16) lut[threadIdx.x] = cb[threadIdx.x] * 0.08838834764831845f; // 1/sqrt(128)
    __syncthreads();
    long idx = (long)blockIdx.x * blockDim.x + threadIdx.x;
    long total = (long)N * (K >> 3);
    if (idx >= total) return;
    int4 pk = reinterpret_cast<const int4*>(packed)[idx];
    long p0 = idx * 4;               // packed element index
    int Kh = K >> 1;
    int n  = (int)(p0 / Kh);
    int k0 = (int)(p0 % Kh) * 2;     // first k (8 consecutive k, same group)
    float s = norms[(long)n * (K >> 7) + (k0 >> 7)];
    uint4 o;
    o.x = pack2(pk.x, lut, s);
    o.y = pack2(pk.y, lut, s);
    o.z = pack2(pk.z, lut, s);
    o.w = pack2(pk.w, lut, s);
    reinterpret_cast<uint4*>(out)[idx] = o;
}

// ---------------- GEMM: C[M,N] = A[M,K] * B[N,K]^T, fp16 in, fp32 accum ----------------
#define STAGES 4
#define SLDK   40   // smem row stride in halves (80B: conflict-free for ldmatrix)

__device__ __forceinline__ void cpasync16(void* s, const void* g) {
    uint32_t sa = (uint32_t)__cvta_generic_to_shared(s);
    asm volatile("cp.async.cg.shared.global [%0], [%1], 16;\n" :: "r"(sa), "l"(g));
}
__device__ __forceinline__ void ldm4(uint32_t& r0, uint32_t& r1, uint32_t& r2, uint32_t& r3,
                                     const void* p) {
    uint32_t a = (uint32_t)__cvta_generic_to_shared(p);
    asm volatile("ldmatrix.sync.aligned.m8n8.x4.shared.b16 {%0,%1,%2,%3}, [%4];"
                 : "=r"(r0), "=r"(r1), "=r"(r2), "=r"(r3) : "r"(a));
}
__device__ __forceinline__ void mma16816(float* c, const uint32_t* a, const uint32_t* b) {
    asm volatile(
        "mma.sync.aligned.m16n8k16.row.col.f32.f16.f16.f32 "
        "{%0,%1,%2,%3}, {%4,%5,%6,%7}, {%8,%9}, {%0,%1,%2,%3};"
        : "+f"(c[0]), "+f"(c[1]), "+f"(c[2]), "+f"(c[3])
        : "r"(a[0]), "r"(a[1]), "r"(a[2]), "r"(a[3]), "r"(b[0]), "r"(b[1]));
}

// EPI: 0 = float out, +bias (down). 1 = half out (rot GEMMs).
//      2 = half out, +bias (gate).  3 = half out, silu(aux)*(acc+bias) (up/SwiGLU).
// NF:  n-fragments (n8) per warp. 4 -> BN=128, 2 -> BN=64.
template<int EPI, int NF>
__global__ void __launch_bounds__(256, 2)
k_gemm(const __half* __restrict__ A, const __half* __restrict__ B,
       const float* __restrict__ bias, const __half* __restrict__ aux,
       void* __restrict__ C,
       int M, int N, int K, int lda, int ldb, int ldc,
       int aColOff, int bBatch, int cColOff) {
    constexpr int BN = NF * 32;          // 4 warps along n, each NF*8 cols
    extern __shared__ __half sm[];
    __half* As = sm;
    __half* Bs = sm + STAGES * 128 * SLDK;

    const int tid = threadIdx.x, lane = tid & 31, wid = tid >> 5;
    const int wm = wid >> 2, wn = wid & 3;              // 2 x 4 warps
    const int m0 = blockIdx.x * 128, n0 = blockIdx.y * BN;
    const __half* Ab = A + (size_t)blockIdx.z * aColOff;
    const __half* Bb = B + (size_t)blockIdx.z * bBatch;
    const int ktiles = K >> 5;

    float acc[4][NF][4];
#pragma unroll
    for (int i = 0; i < 4; i++)
#pragma unroll
        for (int j = 0; j < NF; j++)
#pragma unroll
            for (int k = 0; k < 4; k++) acc[i][j][k] = 0.f;

    const int c1 = tid, c2 = tid + 256;
    const int r1 = c1 >> 2, kc1 = c1 & 3, r2 = c2 >> 2, kc2 = c2 & 3;

    auto issue = [&](int t) {
        int slot = t & (STAGES - 1);
        __half* as = As + slot * 128 * SLDK;
        __half* bs = Bs + slot * BN * SLDK;
        int k0 = t << 5;
        cpasync16(as + r1 * SLDK + kc1 * 8, Ab + (size_t)(m0 + r1) * lda + k0 + kc1 * 8);
        cpasync16(as + r2 * SLDK + kc2 * 8, Ab + (size_t)(m0 + r2) * lda + k0 + kc2 * 8);
        cpasync16(bs + r1 * SLDK + kc1 * 8, Bb + (size_t)(n0 + (r1 & (BN - 1))) * ldb + k0 + kc1 * 8);
        if (NF == 4)
            cpasync16(bs + r2 * SLDK + kc2 * 8, Bb + (size_t)(n0 + r2) * ldb + k0 + kc2 * 8);
    };

#pragma unroll
    for (int t = 0; t < STAGES - 1; t++) {
        if (t < ktiles) issue(t);
        asm volatile("cp.async.commit_group;");
    }

    for (int t = 0; t < ktiles; t++) {
        asm volatile("cp.async.wait_group %0;" :: "n"(STAGES - 2));
        __syncthreads();
        int nt = t + STAGES - 1;
        if (nt < ktiles) issue(nt);
        asm volatile("cp.async.commit_group;");

        int slot = t & (STAGES - 1);
        const __half* as = As + slot * 128 * SLDK;
        const __half* bs = Bs + slot * BN * SLDK;
#pragma unroll
        for (int kk = 0; kk < 2; kk++) {
            uint32_t af[4][4], bf[NF][2];
#pragma unroll
            for (int mi = 0; mi < 4; mi++) {
                const __half* p = as + (wm * 64 + mi * 16 + (lane & 15)) * SLDK
                                     + kk * 16 + (lane >> 4) * 8;
                ldm4(af[mi][0], af[mi][1], af[mi][2], af[mi][3], p);
            }
#pragma unroll
            for (int nb = 0; nb < NF / 2; nb++) {
                const __half* p = bs + (wn * (NF * 8) + nb * 16 + (lane & 7) + ((lane >> 4) << 3)) * SLDK
                                     + kk * 16 + (((lane >> 3) & 1) << 3);
                uint32_t q0, q1, q2, q3;
                ldm4(q0, q1, q2, q3, p);
                bf[nb * 2][0] = q0; bf[nb * 2][1] = q1;
                bf[nb * 2 + 1][0] = q2; bf[nb * 2 + 1][1] = q3;
            }
#pragma unroll
            for (int mi = 0; mi < 4; mi++)
#pragma unroll
                for (int ni = 0; ni < NF; ni++)
                    mma16816(acc[mi][ni], af[mi], bf[ni]);
        }
    }

    // epilogue
    const int crow = wm * 64 + (lane >> 2);
    const int ccol = wn * (NF * 8) + (lane & 3) * 2;
#pragma unroll
    for (int mi = 0; mi < 4; mi++) {
#pragma unroll
        for (int ni = 0; ni < NF; ni++) {
            int gr = m0 + crow + mi * 16;
            int gc = n0 + ccol + ni * 8 + blockIdx.z * cColOff;
            float v0 = acc[mi][ni][0], v1 = acc[mi][ni][1];
            float v2 = acc[mi][ni][2], v3 = acc[mi][ni][3];
            if (EPI == 0 || EPI == 2 || EPI == 3) {
                float b0 = bias[gc], b1 = bias[gc + 1];
                v0 += b0; v1 += b1; v2 += b0; v3 += b1;
            }
            if (EPI == 3) {
                __half2 ga = *reinterpret_cast<const __half2*>(&aux[(size_t)gr * ldc + gc]);
                __half2 gb = *reinterpret_cast<const __half2*>(&aux[(size_t)(gr + 8) * ldc + gc]);
                float g0 = __half2float(ga.x), g1 = __half2float(ga.y);
                float g2 = __half2float(gb.x), g3 = __half2float(gb.y);
                v0 *= g0 / (1.f + __expf(-g0));
                v1 *= g1 / (1.f + __expf(-g1));
                v2 *= g2 / (1.f + __expf(-g2));
                v3 *= g3 / (1.f + __expf(-g3));
            }
            if (EPI == 0) {
                float* Cf = (float*)C;
                *reinterpret_cast<float2*>(&Cf[(size_t)gr * ldc + gc])       = make_float2(v0, v1);
                *reinterpret_cast<float2*>(&Cf[(size_t)(gr + 8) * ldc + gc]) = make_float2(v2, v3);
            } else {
                __half* Ch = (__half*)C;
                *reinterpret_cast<__half2*>(&Ch[(size_t)gr * ldc + gc])       = __floats2half2_rn(v0, v1);
                *reinterpret_cast<__half2*>(&Ch[(size_t)(gr + 8) * ldc + gc]) = __floats2half2_rn(v2, v3);
            }
        }
    }
}

// ---------------- host ----------------
template<typename T>
static void* symaddr(T& sym_) {
    void* p = nullptr;
    cudaGetSymbolAddress(&p, sym_);
    return p;
}

extern "C" void kernel_launch(void* const* d_in, const int* in_sizes, int n_in,
                              void* d_out, int out_size) {
    (void)in_sizes; (void)n_in; (void)out_size;
    const float* x     = (const float*)d_in[0];
    const float* cb    = (const float*)d_in[1];
    const float* gnorm = (const float*)d_in[2];
    const float* gbias = (const float*)d_in[3];
    const float* unorm = (const float*)d_in[4];
    const float* ubias = (const float*)d_in[5];
    const float* dnorm = (const float*)d_in[6];
    const float* dbias = (const float*)d_in[7];
    const float* rotg  = (const float*)d_in[8];
    const float* rotu  = (const float*)d_in[9];
    const float* rotd  = (const float*)d_in[10];
    const int*   gp    = (const int*)d_in[11];
    const int*   up_   = (const int*)d_in[12];
    const int*   dp    = (const int*)d_in[13];
    float* out = (float*)d_out;

    __half* xh    = (__half*)symaddr(g_x_h);
    __half* rgh   = (__half*)symaddr(g_rotg_h);
    __half* ruh   = (__half*)symaddr(g_rotu_h);
    __half* rdh   = (__half*)symaddr(g_rotd_h);
    __half* Wg    = (__half*)symaddr(g_Wg);
    __half* Wu    = (__half*)symaddr(g_Wu);
    __half* Wd    = (__half*)symaddr(g_Wd);
    __half* xrg   = (__half*)symaddr(g_xrg);
    __half* xru   = (__half*)symaddr(g_xru);
    __half* gateh = (__half*)symaddr(g_gate);
    __half* hh    = (__half*)symaddr(g_h);
    __half* hr    = (__half*)symaddr(g_hr);

    const int TPB = 256;
    const int smemB128 = STAGES * (128 + 128) * SLDK * (int)sizeof(__half); // 81920
    const int smemB64  = STAGES * (128 + 64)  * SLDK * (int)sizeof(__half); // 61440
    cudaFuncSetAttribute(k_gemm<0, 2>, cudaFuncAttributeMaxDynamicSharedMemorySize, smemB64);
    cudaFuncSetAttribute(k_gemm<1, 4>, cudaFuncAttributeMaxDynamicSharedMemorySize, smemB128);
    cudaFuncSetAttribute(k_gemm<2, 4>, cudaFuncAttributeMaxDynamicSharedMemorySize, smemB128);
    cudaFuncSetAttribute(k_gemm<3, 4>, cudaFuncAttributeMaxDynamicSharedMemorySize, smemB128);

    // fp32 -> fp16 converts
    int n4;
    n4 = BB * DIN / 4;
    k_convert<<<(n4 + TPB - 1) / TPB, TPB>>>((const float4*)x, (__half2*)xh, n4);
    n4 = NGIN * 128 * 128 / 4;
    k_convert<<<(n4 + TPB - 1) / TPB, TPB>>>((const float4*)rotg, (__half2*)rgh, n4);
    k_convert<<<(n4 + TPB - 1) / TPB, TPB>>>((const float4*)rotu, (__half2*)ruh, n4);
    n4 = NGINT * 128 * 128 / 4;
    k_convert<<<(n4 + TPB - 1) / TPB, TPB>>>((const float4*)rotd, (__half2*)rdh, n4);

    // dequant weights (scaled by norms/sqrt(128))
    k_dequant<<<(int)((long)DINT * DIN / 8 / TPB), TPB>>>(gp, cb, gnorm, Wg, DINT, DIN);
    k_dequant<<<(int)((long)DINT * DIN / 8 / TPB), TPB>>>(up_, cb, unorm, Wu, DINT, DIN);
    k_dequant<<<(int)((long)DIN * DINT / 8 / TPB), TPB>>>(dp, cb, dnorm, Wd, DIN, DINT);

    // per-group rotations of x (batched GEMM: C = x_g @ R_g^T)
    k_gemm<1, 4><<<dim3(BB / 128, 1, NGIN), 256, smemB128>>>(
        xh, rgh, nullptr, nullptr, xrg, BB, 128, 128, DIN, 128, DIN, 128, 128 * 128, 128);
    k_gemm<1, 4><<<dim3(BB / 128, 1, NGIN), 256, smemB128>>>(
        xh, ruh, nullptr, nullptr, xru, BB, 128, 128, DIN, 128, DIN, 128, 128 * 128, 128);

    // gate = xrg @ Wg^T + gbias  (fp16 out)
    k_gemm<2, 4><<<dim3(BB / 128, DINT / 128, 1), 256, smemB128>>>(
        xrg, Wg, gbias, nullptr, gateh, BB, DINT, DIN, DIN, DIN, DINT, 0, 0, 0);

    // h = silu(gate) * (xru @ Wu^T + ubias)
    k_gemm<3, 4><<<dim3(BB / 128, DINT / 128, 1), 256, smemB128>>>(
        xru, Wu, ubias, gateh, hh, BB, DINT, DIN, DIN, DIN, DINT, 0, 0, 0);

    // per-group rotation of h
    k_gemm<1, 4><<<dim3(BB / 128, 1, NGINT), 256, smemB128>>>(
        hh, rdh, nullptr, nullptr, hr, BB, 128, 128, DINT, 128, DINT, 128, 128 * 128, 128);

    // out = hr @ Wd^T + dbias  (fp32 out) — BN=64 -> 256 CTAs -> occ-2 regime
    k_gemm<0, 2><<<dim3(BB / 128, DIN / 64, 1), 256, smemB64>>>(
        hr, Wd, dbias, nullptr, out, BB, DIN, DINT, DINT, DINT, DIN, 0, 0, 0);
}

// round 5
// speedup vs baseline: 1.0617x; 1.0617x over previous
#include <cuda_runtime.h>
#include <cuda_fp16.h>
#include <cstdint>
#include <math.h>

// ---------------- problem dims ----------------
#define BB    1024
#define DIN   2048
#define DINT  8192
#define NGIN  16          // DIN/128
#define NGINT 64          // DINT/128

// ---------------- scratch (device globals; no allocation allowed) ----------------
__device__ __half g_x_h  [BB * DIN];              // x in fp16
__device__ __half g_rotg_h[NGIN  * 128 * 128];
__device__ __half g_rotu_h[NGIN  * 128 * 128];
__device__ __half g_rotd_h[NGINT * 128 * 128];
__device__ __half g_Wg   [DINT * DIN];            // dequantized, scaled weights
__device__ __half g_Wu   [DINT * DIN];
__device__ __half g_Wd   [DIN * DINT];
__device__ __half g_xrg  [BB * DIN];              // rotated x (gate path)
__device__ __half g_xru  [BB * DIN];              // rotated x (up path)
__device__ __half g_gate [BB * DINT];             // gate + bias (pre-silu), fp16
__device__ __half g_h    [BB * DINT];             // silu(gate)*up
__device__ __half g_hr   [BB * DINT];             // rotated h
__device__ float  g_part [2 * BB * DIN];          // split-K partials for down GEMM

// ---------------- small kernels ----------------
__global__ void k_convert(const float4* __restrict__ in, __half2* __restrict__ out, int n4) {
    int i = blockIdx.x * blockDim.x + threadIdx.x;
    if (i >= n4) return;
    float4 v = in[i];
    out[2 * i]     = __floats2half2_rn(v.x, v.y);
    out[2 * i + 1] = __floats2half2_rn(v.z, v.w);
}

__device__ __forceinline__ uint32_t pack2(int v, const float* lut, float s) {
    __half2 h = __floats2half2_rn(lut[v & 15] * s, lut[(v >> 4) & 15] * s);
    return *reinterpret_cast<uint32_t*>(&h);
}

// Each thread: 4 packed int32 (one byte each = 2 nibbles) -> 8 fp16 weights.
__global__ void k_dequant(const int* __restrict__ packed, const float* __restrict__ cb,
                          const float* __restrict__ norms, __half* __restrict__ out,
                          int N, int K) {
    __shared__ float lut[16];
    if (threadIdx.x < 16) lut[threadIdx.x] = cb[threadIdx.x] * 0.08838834764831845f; // 1/sqrt(128)
    __syncthreads();
    long idx = (long)blockIdx.x * blockDim.x + threadIdx.x;
    long total = (long)N * (K >> 3);
    if (idx >= total) return;
    int4 pk = reinterpret_cast<const int4*>(packed)[idx];
    long p0 = idx * 4;               // packed element index
    int Kh = K >> 1;
    int n  = (int)(p0 / Kh);
    int k0 = (int)(p0 % Kh) * 2;     // first k (8 consecutive k, same group)
    float s = norms[(long)n * (K >> 7) + (k0 >> 7)];
    uint4 o;
    o.x = pack2(pk.x, lut, s);
    o.y = pack2(pk.y, lut, s);
    o.z = pack2(pk.z, lut, s);
    o.w = pack2(pk.w, lut, s);
    reinterpret_cast<uint4*>(out)[idx] = o;
}

// split-K reduce: out = p0 + p1 + bias (deterministic order)
__global__ void k_reduce2(const float4* __restrict__ p0, const float4* __restrict__ p1,
                          const float* __restrict__ bias, float4* __restrict__ out,
                          int n4, int ldc4) {
    int i = blockIdx.x * blockDim.x + threadIdx.x;
    if (i >= n4) return;
    float4 a = p0[i], b = p1[i];
    int c4 = i % ldc4;
    const float4 bv = reinterpret_cast<const float4*>(bias)[c4];
    float4 o;
    o.x = a.x + b.x + bv.x;
    o.y = a.y + b.y + bv.y;
    o.z = a.z + b.z + bv.z;
    o.w = a.w + b.w + bv.w;
    out[i] = o;
}

// ---------------- GEMM: C[M,N] = A[M,K] * B[N,K]^T, fp16 in, fp32 accum ----------------
#define STAGES 4
#define SLDK   40   // smem row stride in halves (80B: conflict-free for ldmatrix)

__device__ __forceinline__ void cpasync16(void* s, const void* g) {
    uint32_t sa = (uint32_t)__cvta_generic_to_shared(s);
    asm volatile("cp.async.cg.shared.global [%0], [%1], 16;\n" :: "r"(sa), "l"(g));
}
__device__ __forceinline__ void ldm4(uint32_t& r0, uint32_t& r1, uint32_t& r2, uint32_t& r3,
                                     const void* p) {
    uint32_t a = (uint32_t)__cvta_generic_to_shared(p);
    asm volatile("ldmatrix.sync.aligned.m8n8.x4.shared.b16 {%0,%1,%2,%3}, [%4];"
                 : "=r"(r0), "=r"(r1), "=r"(r2), "=r"(r3) : "r"(a));
}
__device__ __forceinline__ void mma16816(float* c, const uint32_t* a, const uint32_t* b) {
    asm volatile(
        "mma.sync.aligned.m16n8k16.row.col.f32.f16.f16.f32 "
        "{%0,%1,%2,%3}, {%4,%5,%6,%7}, {%8,%9}, {%0,%1,%2,%3};"
        : "+f"(c[0]), "+f"(c[1]), "+f"(c[2]), "+f"(c[3])
        : "r"(a[0]), "r"(a[1]), "r"(a[2]), "r"(a[3]), "r"(b[0]), "r"(b[1]));
}

// EPI: 0 = float out +bias. 1 = half out (rot GEMMs). 2 = half out +bias (gate).
//      3 = half out, silu(aux)*(acc+bias) (up/SwiGLU). 4 = raw float out (split-K partial).
template<int EPI>
__global__ void __launch_bounds__(256, 2)
k_gemm(const __half* __restrict__ A, const __half* __restrict__ B,
       const float* __restrict__ bias, const __half* __restrict__ aux,
       void* __restrict__ C,
       int M, int N, int K, int lda, int ldb, int ldc,
       int aColOff, int bBatch, int cColOff, int cBatch) {
    extern __shared__ __half sm[];
    __half* As = sm;
    __half* Bs = sm + STAGES * 128 * SLDK;

    const int tid = threadIdx.x, lane = tid & 31, wid = tid >> 5;
    const int wm = wid >> 2, wn = wid & 3;              // 2 x 4 warps; warp tile 64x32
    const int m0 = blockIdx.x * 128, n0 = blockIdx.y * 128;
    const __half* Ab = A + (size_t)blockIdx.z * aColOff;
    const __half* Bb = B + (size_t)blockIdx.z * bBatch;
    const int ktiles = K >> 5;

    float acc[4][4][4];
#pragma unroll
    for (int i = 0; i < 4; i++)
#pragma unroll
        for (int j = 0; j < 4; j++)
#pragma unroll
            for (int k = 0; k < 4; k++) acc[i][j][k] = 0.f;

    const int c1 = tid, c2 = tid + 256;
    const int r1 = c1 >> 2, kc1 = c1 & 3, r2 = c2 >> 2, kc2 = c2 & 3;

    auto issue = [&](int t) {
        int slot = t & (STAGES - 1);
        __half* as = As + slot * 128 * SLDK;
        __half* bs = Bs + slot * 128 * SLDK;
        int k0 = t << 5;
        cpasync16(as + r1 * SLDK + kc1 * 8, Ab + (size_t)(m0 + r1) * lda + k0 + kc1 * 8);
        cpasync16(as + r2 * SLDK + kc2 * 8, Ab + (size_t)(m0 + r2) * lda + k0 + kc2 * 8);
        cpasync16(bs + r1 * SLDK + kc1 * 8, Bb + (size_t)(n0 + r1) * ldb + k0 + kc1 * 8);
        cpasync16(bs + r2 * SLDK + kc2 * 8, Bb + (size_t)(n0 + r2) * ldb + k0 + kc2 * 8);
    };

#pragma unroll
    for (int t = 0; t < STAGES - 1; t++) {
        if (t < ktiles) issue(t);
        asm volatile("cp.async.commit_group;");
    }

    for (int t = 0; t < ktiles; t++) {
        asm volatile("cp.async.wait_group %0;" :: "n"(STAGES - 2));
        __syncthreads();
        int nt = t + STAGES - 1;
        if (nt < ktiles) issue(nt);
        asm volatile("cp.async.commit_group;");

        int slot = t & (STAGES - 1);
        const __half* as = As + slot * 128 * SLDK;
        const __half* bs = Bs + slot * 128 * SLDK;
#pragma unroll
        for (int kk = 0; kk < 2; kk++) {
            uint32_t af[4][4], bf[4][2];
#pragma unroll
            for (int mi = 0; mi < 4; mi++) {
                const __half* p = as + (wm * 64 + mi * 16 + (lane & 15)) * SLDK
                                     + kk * 16 + (lane >> 4) * 8;
                ldm4(af[mi][0], af[mi][1], af[mi][2], af[mi][3], p);
            }
#pragma unroll
            for (int nb = 0; nb < 2; nb++) {
                const __half* p = bs + (wn * 32 + nb * 16 + (lane & 7) + ((lane >> 4) << 3)) * SLDK
                                     + kk * 16 + (((lane >> 3) & 1) << 3);
                uint32_t q0, q1, q2, q3;
                ldm4(q0, q1, q2, q3, p);
                bf[nb * 2][0] = q0; bf[nb * 2][1] = q1;
                bf[nb * 2 + 1][0] = q2; bf[nb * 2 + 1][1] = q3;
            }
#pragma unroll
            for (int mi = 0; mi < 4; mi++)
#pragma unroll
                for (int ni = 0; ni < 4; ni++)
                    mma16816(acc[mi][ni], af[mi], bf[ni]);
        }
    }

    // epilogue
    const int crow = wm * 64 + (lane >> 2);
    const int ccol = wn * 32 + (lane & 3) * 2;
#pragma unroll
    for (int mi = 0; mi < 4; mi++) {
#pragma unroll
        for (int ni = 0; ni < 4; ni++) {
            int gr = m0 + crow + mi * 16;
            int gc = n0 + ccol + ni * 8 + blockIdx.z * cColOff;
            float v0 = acc[mi][ni][0], v1 = acc[mi][ni][1];
            float v2 = acc[mi][ni][2], v3 = acc[mi][ni][3];
            if (EPI == 0 || EPI == 2 || EPI == 3) {
                float b0 = bias[gc], b1 = bias[gc + 1];
                v0 += b0; v1 += b1; v2 += b0; v3 += b1;
            }
            if (EPI == 3) {
                __half2 ga = *reinterpret_cast<const __half2*>(&aux[(size_t)gr * ldc + gc]);
                __half2 gb = *reinterpret_cast<const __half2*>(&aux[(size_t)(gr + 8) * ldc + gc]);
                float g0 = __half2float(ga.x), g1 = __half2float(ga.y);
                float g2 = __half2float(gb.x), g3 = __half2float(gb.y);
                v0 *= g0 / (1.f + __expf(-g0));
                v1 *= g1 / (1.f + __expf(-g1));
                v2 *= g2 / (1.f + __expf(-g2));
                v3 *= g3 / (1.f + __expf(-g3));
            }
            if (EPI == 0 || EPI == 4) {
                float* Cf = (float*)C + (size_t)blockIdx.z * cBatch;
                *reinterpret_cast<float2*>(&Cf[(size_t)gr * ldc + gc])       = make_float2(v0, v1);
                *reinterpret_cast<float2*>(&Cf[(size_t)(gr + 8) * ldc + gc]) = make_float2(v2, v3);
            } else {
                __half* Ch = (__half*)C;
                *reinterpret_cast<__half2*>(&Ch[(size_t)gr * ldc + gc])       = __floats2half2_rn(v0, v1);
                *reinterpret_cast<__half2*>(&Ch[(size_t)(gr + 8) * ldc + gc]) = __floats2half2_rn(v2, v3);
            }
        }
    }
}

// ---------------- host ----------------
template<typename T>
static void* symaddr(T& sym_) {
    void* p = nullptr;
    cudaGetSymbolAddress(&p, sym_);
    return p;
}

extern "C" void kernel_launch(void* const* d_in, const int* in_sizes, int n_in,
                              void* d_out, int out_size) {
    (void)in_sizes; (void)n_in; (void)out_size;
    const float* x     = (const float*)d_in[0];
    const float* cb    = (const float*)d_in[1];
    const float* gnorm = (const float*)d_in[2];
    const float* gbias = (const float*)d_in[3];
    const float* unorm = (const float*)d_in[4];
    const float* ubias = (const float*)d_in[5];
    const float* dnorm = (const float*)d_in[6];
    const float* dbias = (const float*)d_in[7];
    const float* rotg  = (const float*)d_in[8];
    const float* rotu  = (const float*)d_in[9];
    const float* rotd  = (const float*)d_in[10];
    const int*   gp    = (const int*)d_in[11];
    const int*   up_   = (const int*)d_in[12];
    const int*   dp    = (const int*)d_in[13];
    float* out = (float*)d_out;

    __half* xh    = (__half*)symaddr(g_x_h);
    __half* rgh   = (__half*)symaddr(g_rotg_h);
    __half* ruh   = (__half*)symaddr(g_rotu_h);
    __half* rdh   = (__half*)symaddr(g_rotd_h);
    __half* Wg    = (__half*)symaddr(g_Wg);
    __half* Wu    = (__half*)symaddr(g_Wu);
    __half* Wd    = (__half*)symaddr(g_Wd);
    __half* xrg   = (__half*)symaddr(g_xrg);
    __half* xru   = (__half*)symaddr(g_xru);
    __half* gateh = (__half*)symaddr(g_gate);
    __half* hh    = (__half*)symaddr(g_h);
    __half* hr    = (__half*)symaddr(g_hr);
    float*  part  = (float*)symaddr(g_part);

    const int TPB = 256;
    const int smemB = STAGES * 2 * 128 * SLDK * (int)sizeof(__half); // 81920
    cudaFuncSetAttribute(k_gemm<0>, cudaFuncAttributeMaxDynamicSharedMemorySize, smemB);
    cudaFuncSetAttribute(k_gemm<1>, cudaFuncAttributeMaxDynamicSharedMemorySize, smemB);
    cudaFuncSetAttribute(k_gemm<2>, cudaFuncAttributeMaxDynamicSharedMemorySize, smemB);
    cudaFuncSetAttribute(k_gemm<3>, cudaFuncAttributeMaxDynamicSharedMemorySize, smemB);
    cudaFuncSetAttribute(k_gemm<4>, cudaFuncAttributeMaxDynamicSharedMemorySize, smemB);

    // fp32 -> fp16 converts
    int n4;
    n4 = BB * DIN / 4;
    k_convert<<<(n4 + TPB - 1) / TPB, TPB>>>((const float4*)x, (__half2*)xh, n4);
    n4 = NGIN * 128 * 128 / 4;
    k_convert<<<(n4 + TPB - 1) / TPB, TPB>>>((const float4*)rotg, (__half2*)rgh, n4);
    k_convert<<<(n4 + TPB - 1) / TPB, TPB>>>((const float4*)rotu, (__half2*)ruh, n4);
    n4 = NGINT * 128 * 128 / 4;
    k_convert<<<(n4 + TPB - 1) / TPB, TPB>>>((const float4*)rotd, (__half2*)rdh, n4);

    // dequant weights (scaled by norms/sqrt(128))
    k_dequant<<<(int)((long)DINT * DIN / 8 / TPB), TPB>>>(gp, cb, gnorm, Wg, DINT, DIN);
    k_dequant<<<(int)((long)DINT * DIN / 8 / TPB), TPB>>>(up_, cb, unorm, Wu, DINT, DIN);
    k_dequant<<<(int)((long)DIN * DINT / 8 / TPB), TPB>>>(dp, cb, dnorm, Wd, DIN, DINT);

    // per-group rotations of x (batched GEMM: C = x_g @ R_g^T)
    k_gemm<1><<<dim3(BB / 128, 1, NGIN), 256, smemB>>>(
        xh, rgh, nullptr, nullptr, xrg, BB, 128, 128, DIN, 128, DIN, 128, 128 * 128, 128, 0);
    k_gemm<1><<<dim3(BB / 128, 1, NGIN), 256, smemB>>>(
        xh, ruh, nullptr, nullptr, xru, BB, 128, 128, DIN, 128, DIN, 128, 128 * 128, 128, 0);

    // gate = xrg @ Wg^T + gbias  (fp16 out)
    k_gemm<2><<<dim3(BB / 128, DINT / 128, 1), 256, smemB>>>(
        xrg, Wg, gbias, nullptr, gateh, BB, DINT, DIN, DIN, DIN, DINT, 0, 0, 0, 0);

    // h = silu(gate) * (xru @ Wu^T + ubias)
    k_gemm<3><<<dim3(BB / 128, DINT / 128, 1), 256, smemB>>>(
        xru, Wu, ubias, gateh, hh, BB, DINT, DIN, DIN, DIN, DINT, 0, 0, 0, 0);

    // per-group rotation of h
    k_gemm<1><<<dim3(BB / 128, 1, NGINT), 256, smemB>>>(
        hh, rdh, nullptr, nullptr, hr, BB, 128, 128, DINT, 128, DINT, 128, 128 * 128, 128, 0);

    // down GEMM split-K=2: partials (8,16,2) = 256 CTAs -> occ-2 regime, same traffic
    k_gemm<4><<<dim3(BB / 128, DIN / 128, 2), 256, smemB>>>(
        hr, Wd, nullptr, nullptr, part, BB, DIN, DINT / 2, DINT, DINT, DIN,
        DINT / 2, DINT / 2, 0, BB * DIN);

    // out = part0 + part1 + dbias
    {
        int n4r = BB * DIN / 4;
        k_reduce2<<<(n4r + TPB - 1) / TPB, TPB>>>(
            (const float4*)part, (const float4*)(part + BB * DIN), dbias,
            (float4*)out, n4r, DIN / 4);
    }
}